// round 1
// baseline (speedup 1.0000x reference)
#include <cuda_runtime.h>
#include <math.h>

#define Hh 2
#define Bb 8
#define Nn 2048
#define Dd 64
#define Qq 16
#define Cc 129
#define C8v 16
#define Kk 8192
#define VP 132   // padded stride for v / comb rows (float4 friendly)
#define NEGV (-9.0e15f)
#define NROW (Bb*Nn)

// ---------------- device scratch (static: allowed) ----------------
__device__ float g_q[Hh*NROW*C8v];
__device__ float g_k[Hh*NROW*C8v];
__device__ float g_v[Hh*NROW*VP];
__device__ float g_comb[NROW*VP];
__device__ float g_u[Kk*Dd];
__device__ float g_hsel[Kk*Dd];

// =================== 1) QKV projection ===================
// grid (512, 3): y=0 -> q&k (64 outs), y=1 -> v head0, y=2 -> v head1
struct ProjSmem {
    float comb[Cc][36];   // transposed [c][r], padded rows for banks+align
    float W[Cc][VP];
    float bias[VP];
};

__global__ void proj_kernel(const float* __restrict__ x, const float* __restrict__ h,
                            const float* __restrict__ Wq, const float* __restrict__ bq,
                            const float* __restrict__ Wk, const float* __restrict__ bk,
                            const float* __restrict__ Wv, const float* __restrict__ bv) {
    extern __shared__ char sm_raw[];
    ProjSmem& sm = *reinterpret_cast<ProjSmem*>(sm_raw);
    const int t = threadIdx.x;
    const int row0 = blockIdx.x * 32;
    const int y = blockIdx.y;

    // load combined tile transposed: comb[c][r]
    for (int idx = t; idx < 32 * Cc; idx += 256) {
        int r = idx / Cc, c = idx % Cc;
        int row = row0 + r;
        float v = (c < 65) ? x[row * 65 + c] : h[row * 64 + (c - 65)];
        sm.comb[c][r] = v;
    }
    if (y == 0) {
        for (int idx = t; idx < Cc * 64; idx += 256) {
            int c = idx / 64, o = idx % 64;
            float w;
            if (o < 32)      w = Wq[((o >> 4) * Cc + c) * C8v + (o & 15)];
            else { int o2 = o - 32; w = Wk[((o2 >> 4) * Cc + c) * C8v + (o2 & 15)]; }
            sm.W[c][o] = w;
        }
        if (t < 64) {
            float b;
            if (t < 32)      b = bq[(t >> 4) * C8v + (t & 15)];
            else { int o2 = t - 32; b = bk[(o2 >> 4) * C8v + (o2 & 15)]; }
            sm.bias[t] = b;
        }
    } else {
        int hh = y - 1;
        for (int idx = t; idx < Cc * VP; idx += 256) {
            int c = idx / VP, o = idx % VP;
            sm.W[c][o] = (o < Cc) ? Wv[(hh * Cc + c) * Cc + o] : 0.f;
        }
        for (int o = t; o < VP; o += 256) sm.bias[o] = (o < Cc) ? bv[hh * Cc + o] : 0.f;
    }
    __syncthreads();

    if (y == 0) {
        int r = t >> 3, og = t & 7;
        int c0 = og * 8;
        float acc[8];
#pragma unroll
        for (int j = 0; j < 8; j++) acc[j] = 0.f;
        for (int c = 0; c < Cc; c++) {
            float a = sm.comb[c][r];
#pragma unroll
            for (int j = 0; j < 8; j++) acc[j] += a * sm.W[c][c0 + j];
        }
        int row = row0 + r;
#pragma unroll
        for (int j = 0; j < 8; j++) {
            int o = c0 + j;
            float val = acc[j] + sm.bias[o];
            if (o < 32) {
                g_q[(((o >> 4) * NROW) + row) * C8v + (o & 15)] = val;
            } else {
                int o2 = o - 32;
                g_k[(((o2 >> 4) * NROW) + row) * C8v + (o2 & 15)] = val;
            }
        }
    } else {
        int hh = y - 1;
        int r = t >> 3, og = t & 7;
        int c0 = og * 16;
        int xcol = 128 + og;   // og<4 handles cols 128..131
        float acc[17];
#pragma unroll
        for (int j = 0; j < 17; j++) acc[j] = 0.f;
        for (int c = 0; c < Cc; c++) {
            float a = sm.comb[c][r];
#pragma unroll
            for (int j = 0; j < 16; j++) acc[j] += a * sm.W[c][c0 + j];
            if (og < 4) acc[16] += a * sm.W[c][xcol];
        }
        int row = row0 + r;
        float* dst = &g_v[((hh * NROW) + row) * VP];
#pragma unroll
        for (int j = 0; j < 16; j++) dst[c0 + j] = acc[j] + sm.bias[c0 + j];
        if (og < 4) dst[xcol] = acc[16] + sm.bias[xcol];
    }
}

// =================== 2) fused 2-head attention + head mean ===================
// grid (128 row-tiles, 8 batches), 256 threads. R=16 rows, 64-key tiles.
struct AttnSmem {
    float q[Hh][16][16];
    float k[Hh][64][16];
    float p[Hh][16][65];   // padded rows (bank spread)
    int   adj[16][64];
    float rmax[Hh][16];
    float rsum[Hh][16];
    float fac[Hh][16];
    union Big {
        float v[Hh][64][VP];
        float osh[16][Cc];
    } big;
};

__global__ void attn_kernel(const int* __restrict__ adjg) {
    extern __shared__ char sm_raw[];
    AttnSmem& sm = *reinterpret_cast<AttnSmem*>(sm_raw);
    const int t = threadIdx.x;
    const int warp = t >> 5, lane = t & 31;
    const int hh = lane >> 4, rr = lane & 15;
    const int b = blockIdx.y;
    const int row0 = blockIdx.x * 16;

    // q tile: 512 floats = 128 float4
    if (t < 128) {
        int h_ = t >> 6, r_ = (t >> 2) & 15, d4 = t & 3;
        const float4* src = (const float4*)&g_q[((h_ * NROW) + b * Nn + row0 + r_) * C8v];
        ((float4*)&sm.q[h_][r_][0])[d4] = src[d4];
    }
    if (t < 32) { sm.rmax[t >> 4][t & 15] = -INFINITY; sm.rsum[t >> 4][t & 15] = 0.f; }
    __syncthreads();

    float qreg[16];
#pragma unroll
    for (int d4 = 0; d4 < 4; d4++) {
        float4 qq = ((const float4*)&sm.q[hh][rr][0])[d4];
        qreg[d4 * 4 + 0] = qq.x; qreg[d4 * 4 + 1] = qq.y;
        qreg[d4 * 4 + 2] = qq.z; qreg[d4 * 4 + 3] = qq.w;
    }

    float acc[17];
#pragma unroll
    for (int j = 0; j < 17; j++) acc[j] = 0.f;

    for (int m0 = 0; m0 < Nn; m0 += 64) {
        // ---- loads ----
        for (int idx = t; idx < 512; idx += 256) {  // k tile: 512 float4
            int h_ = idx >> 8, rem = idx & 255, m = rem >> 2, d4 = rem & 3;
            ((float4*)&sm.k[h_][m][0])[d4] =
                ((const float4*)&g_k[((h_ * NROW) + b * Nn + m0 + m) * C8v])[d4];
        }
        for (int idx = t; idx < 4224; idx += 256) { // v tile: 2*64*33 float4
            int h_ = idx / 2112, rem = idx % 2112, m = rem / 33, c4 = rem % 33;
            ((float4*)&sm.big.v[h_][m][0])[c4] =
                ((const float4*)&g_v[((h_ * NROW) + b * Nn + m0 + m) * VP])[c4];
        }
        {
            int r_ = t >> 4, s4 = t & 15;
            ((int4*)&sm.adj[r_][0])[s4] =
                ((const int4*)&adjg[(b * Nn + row0 + r_) * Nn + m0])[s4];
        }
        __syncthreads();

        // ---- scores (thread owns (hh,rr), m = warp*8+mm) ----
#pragma unroll
        for (int mm = 0; mm < 8; mm++) {
            int m = warp * 8 + mm;
            const float4* kp = (const float4*)&sm.k[hh][m][0];
            float s = 0.f;
#pragma unroll
            for (int d4 = 0; d4 < 4; d4++) {
                float4 kk = kp[d4];
                s += qreg[d4 * 4 + 0] * kk.x + qreg[d4 * 4 + 1] * kk.y
                   + qreg[d4 * 4 + 2] * kk.z + qreg[d4 * 4 + 3] * kk.w;
            }
            s *= 0.25f;                       // 1/sqrt(16)
            s = (s > 0.f) ? s : 0.2f * s;     // leaky relu
            if (sm.adj[rr][m] == 0) s = NEGV;
            sm.p[hh][rr][m] = s;
        }
        __syncthreads();

        // ---- online softmax (8-lane groups, 4 rows per warp) ----
        {
            int pair = warp * 4 + (lane >> 3);
            int ph = pair >> 4, pr = pair & 15;
            int ml = lane & 7;
            float* prow = &sm.p[ph][pr][0];
            float vals[8];
            float tmax = -INFINITY;
#pragma unroll
            for (int j = 0; j < 8; j++) { vals[j] = prow[ml + j * 8]; tmax = fmaxf(tmax, vals[j]); }
#pragma unroll
            for (int o = 4; o > 0; o >>= 1)
                tmax = fmaxf(tmax, __shfl_xor_sync(0xffffffffu, tmax, o, 8));
            float oldmax = sm.rmax[ph][pr];
            float newmax = fmaxf(oldmax, tmax);
            float sum = 0.f;
#pragma unroll
            for (int j = 0; j < 8; j++) {
                float e = __expf(vals[j] - newmax);
                prow[ml + j * 8] = e;
                sum += e;
            }
#pragma unroll
            for (int o = 4; o > 0; o >>= 1)
                sum += __shfl_xor_sync(0xffffffffu, sum, o, 8);
            if (ml == 0) {
                float f = __expf(oldmax - newmax);
                sm.fac[ph][pr] = f;
                sm.rsum[ph][pr] = sm.rsum[ph][pr] * f + sum;
                sm.rmax[ph][pr] = newmax;
            }
        }
        __syncthreads();

        // ---- accumulate: thread owns (hh,rr), c-chunk = warp*16 (+col128 for warp0)
        {
            float f = sm.fac[hh][rr];
#pragma unroll
            for (int j = 0; j < 17; j++) acc[j] *= f;
            const float* prow = &sm.p[hh][rr][0];
            const int c0 = warp * 16;
            for (int m = 0; m < 64; m++) {
                float p = prow[m];
                const float4* vp = (const float4*)&sm.big.v[hh][m][c0];
#pragma unroll
                for (int j4 = 0; j4 < 4; j4++) {
                    float4 v4 = vp[j4];
                    acc[j4 * 4 + 0] += p * v4.x; acc[j4 * 4 + 1] += p * v4.y;
                    acc[j4 * 4 + 2] += p * v4.z; acc[j4 * 4 + 3] += p * v4.w;
                }
                if (warp == 0) acc[16] += p * sm.big.v[hh][m][128];
            }
        }
        __syncthreads();
    }

    // ---- finalize: mean over heads, write comb_attn ----
    float inv = 0.5f / sm.rsum[hh][rr];
    if (hh == 0) {
        int c0 = warp * 16;
#pragma unroll
        for (int j = 0; j < 16; j++) sm.big.osh[rr][c0 + j] = acc[j] * inv;
        if (warp == 0) sm.big.osh[rr][128] = acc[16] * inv;
    }
    __syncthreads();
    if (hh == 1) {
        int c0 = warp * 16;
#pragma unroll
        for (int j = 0; j < 16; j++) sm.big.osh[rr][c0 + j] += acc[j] * inv;
        if (warp == 0) sm.big.osh[rr][128] += acc[16] * inv;
    }
    __syncthreads();
    for (int idx = t; idx < 16 * Cc; idx += 256) {
        int r_ = idx / Cc, c = idx % Cc;
        g_comb[(b * Nn + row0 + r_) * VP + c] = sm.big.osh[r_][c];
    }
}

// =================== 3) hypernetwork gates ===================
struct GateSmem {
    float sel[Cc][68];   // transposed [c][r], 64 rows padded
    float qv[Qq][64];    // transposed [q][r]
    float W[Cc][64];
    int   nodes[64];
};

// grid (128, 2): y=0 -> reset gate (produces h_sel), y=1 -> update gate u
__global__ void gate_ru_kernel(const float* __restrict__ qv_g, const int* __restrict__ nodes,
                               const float* __restrict__ W_r, const float* __restrict__ b_r,
                               const float* __restrict__ W_u, const float* __restrict__ b_u,
                               const float* __restrict__ h_g) {
    extern __shared__ char sm_raw[];
    GateSmem& sm = *reinterpret_cast<GateSmem*>(sm_raw);
    const int t = threadIdx.x;
    const int k0 = blockIdx.x * 64;
    const int gate = blockIdx.y;
    const float* W = gate ? W_u : W_r;
    const float* bias = gate ? b_u : b_r;

    if (t < 64) sm.nodes[t] = nodes[k0 + t];
    __syncthreads();
    for (int idx = t; idx < 64 * Cc; idx += 256) {
        int r = idx / Cc, c = idx % Cc;
        sm.sel[c][r] = g_comb[sm.nodes[r] * VP + c];
    }
    for (int idx = t; idx < 64 * Qq; idx += 256) {
        int r = idx / Qq, q = idx % Qq;
        sm.qv[q][r] = qv_g[(k0 + r) * Qq + q];
    }

    const int rg = t >> 4, og = t & 15;
    const int r0 = rg * 4, o0 = og * 4;
    float acc[4][4];
#pragma unroll
    for (int i = 0; i < 4; i++)
#pragma unroll
        for (int j = 0; j < 4; j++) acc[i][j] = 0.f;

    for (int q = 0; q < Qq; q++) {
        __syncthreads();
        for (int idx = t; idx < Cc * 16; idx += 256) {  // 2064 float4
            int c = idx / 16, o4 = idx % 16;
            ((float4*)&sm.W[c][0])[o4] = ((const float4*)&W[(q * Cc + c) * 64])[o4];
        }
        __syncthreads();
        float a2[4][4];
#pragma unroll
        for (int i = 0; i < 4; i++)
#pragma unroll
            for (int j = 0; j < 4; j++) a2[i][j] = 0.f;
        for (int c = 0; c < Cc; c++) {
            float4 a = *(const float4*)&sm.sel[c][r0];
            float4 w = *(const float4*)&sm.W[c][o0];
            float av[4] = {a.x, a.y, a.z, a.w};
            float wv[4] = {w.x, w.y, w.z, w.w};
#pragma unroll
            for (int i = 0; i < 4; i++)
#pragma unroll
                for (int j = 0; j < 4; j++) a2[i][j] += av[i] * wv[j];
        }
        float4 qq = *(const float4*)&sm.qv[q][r0];
        float qvv[4] = {qq.x, qq.y, qq.z, qq.w};
#pragma unroll
        for (int i = 0; i < 4; i++)
#pragma unroll
            for (int j = 0; j < 4; j++) acc[i][j] += qvv[i] * a2[i][j];
    }
    // bias: + qv[r] @ b
    for (int q = 0; q < Qq; q++) {
        float4 bb = *(const float4*)&bias[q * 64 + o0];
        float bv4[4] = {bb.x, bb.y, bb.z, bb.w};
        float4 qq = *(const float4*)&sm.qv[q][r0];
        float qvv[4] = {qq.x, qq.y, qq.z, qq.w};
#pragma unroll
        for (int i = 0; i < 4; i++)
#pragma unroll
            for (int j = 0; j < 4; j++) acc[i][j] += qvv[i] * bv4[j];
    }
#pragma unroll
    for (int i = 0; i < 4; i++) {
        int kidx = k0 + r0 + i;
#pragma unroll
        for (int j = 0; j < 4; j++) {
            int o = o0 + j;
            float z = 1.f / (1.f + __expf(-acc[i][j]));
            if (gate == 0) {
                g_hsel[kidx * 64 + o] = z * h_g[sm.nodes[r0 + i] * 64 + o];
            } else {
                g_u[kidx * 64 + o] = z;
            }
        }
    }
}

// grid (128, 1): candidate gate on sel2 = [x_part, h_sel] + final combine
__global__ void gate_c_kernel(const float* __restrict__ x_g, const float* __restrict__ qv_g,
                              const int* __restrict__ nodes,
                              const float* __restrict__ W_c, const float* __restrict__ b_c,
                              float* __restrict__ out) {
    extern __shared__ char sm_raw[];
    GateSmem& sm = *reinterpret_cast<GateSmem*>(sm_raw);
    const int t = threadIdx.x;
    const int k0 = blockIdx.x * 64;

    if (t < 64) sm.nodes[t] = nodes[k0 + t];
    __syncthreads();
    for (int idx = t; idx < 64 * Cc; idx += 256) {
        int r = idx / Cc, c = idx % Cc;
        float v = (c < 65) ? x_g[sm.nodes[r] * 65 + c]
                           : g_hsel[(k0 + r) * 64 + (c - 65)];
        sm.sel[c][r] = v;
    }
    for (int idx = t; idx < 64 * Qq; idx += 256) {
        int r = idx / Qq, q = idx % Qq;
        sm.qv[q][r] = qv_g[(k0 + r) * Qq + q];
    }

    const int rg = t >> 4, og = t & 15;
    const int r0 = rg * 4, o0 = og * 4;
    float acc[4][4];
#pragma unroll
    for (int i = 0; i < 4; i++)
#pragma unroll
        for (int j = 0; j < 4; j++) acc[i][j] = 0.f;

    for (int q = 0; q < Qq; q++) {
        __syncthreads();
        for (int idx = t; idx < Cc * 16; idx += 256) {
            int c = idx / 16, o4 = idx % 16;
            ((float4*)&sm.W[c][0])[o4] = ((const float4*)&W_c[(q * Cc + c) * 64])[o4];
        }
        __syncthreads();
        float a2[4][4];
#pragma unroll
        for (int i = 0; i < 4; i++)
#pragma unroll
            for (int j = 0; j < 4; j++) a2[i][j] = 0.f;
        for (int c = 0; c < Cc; c++) {
            float4 a = *(const float4*)&sm.sel[c][r0];
            float4 w = *(const float4*)&sm.W[c][o0];
            float av[4] = {a.x, a.y, a.z, a.w};
            float wv[4] = {w.x, w.y, w.z, w.w};
#pragma unroll
            for (int i = 0; i < 4; i++)
#pragma unroll
                for (int j = 0; j < 4; j++) a2[i][j] += av[i] * wv[j];
        }
        float4 qq = *(const float4*)&sm.qv[q][r0];
        float qvv[4] = {qq.x, qq.y, qq.z, qq.w};
#pragma unroll
        for (int i = 0; i < 4; i++)
#pragma unroll
            for (int j = 0; j < 4; j++) acc[i][j] += qvv[i] * a2[i][j];
    }
    for (int q = 0; q < Qq; q++) {
        float4 bb = *(const float4*)&b_c[q * 64 + o0];
        float bv4[4] = {bb.x, bb.y, bb.z, bb.w};
        float4 qq = *(const float4*)&sm.qv[q][r0];
        float qvv[4] = {qq.x, qq.y, qq.z, qq.w};
#pragma unroll
        for (int i = 0; i < 4; i++)
#pragma unroll
            for (int j = 0; j < 4; j++) acc[i][j] += qvv[i] * bv4[j];
    }
#pragma unroll
    for (int i = 0; i < 4; i++) {
        int kidx = k0 + r0 + i;
#pragma unroll
        for (int j = 0; j < 4; j++) {
            int o = o0 + j;
            float cand = tanhf(acc[i][j]);
            float u  = g_u[kidx * 64 + o];
            float hs = g_hsel[kidx * 64 + o];
            out[kidx * 64 + o] = (1.f - u) * hs + u * cand;
        }
    }
}

// =================== launch ===================
extern "C" void kernel_launch(void* const* d_in, const int* in_sizes, int n_in,
                              void* d_out, int out_size) {
    const float* x   = (const float*)d_in[0];
    const float* h   = (const float*)d_in[1];
    const float* qv  = (const float*)d_in[2];
    const int*   adj = (const int*)d_in[3];
    const int*   nodes = (const int*)d_in[4];
    const float* Wq = (const float*)d_in[5];
    const float* bq = (const float*)d_in[6];
    const float* Wk = (const float*)d_in[7];
    const float* bk = (const float*)d_in[8];
    const float* Wv = (const float*)d_in[9];
    const float* bv = (const float*)d_in[10];
    const float* W_r = (const float*)d_in[11];
    const float* b_r = (const float*)d_in[12];
    const float* W_u = (const float*)d_in[13];
    const float* b_u = (const float*)d_in[14];
    const float* W_c = (const float*)d_in[15];
    const float* b_c = (const float*)d_in[16];
    float* out = (float*)d_out;

    cudaFuncSetAttribute(proj_kernel, cudaFuncAttributeMaxDynamicSharedMemorySize, (int)sizeof(ProjSmem));
    cudaFuncSetAttribute(attn_kernel, cudaFuncAttributeMaxDynamicSharedMemorySize, (int)sizeof(AttnSmem));
    cudaFuncSetAttribute(gate_ru_kernel, cudaFuncAttributeMaxDynamicSharedMemorySize, (int)sizeof(GateSmem));
    cudaFuncSetAttribute(gate_c_kernel, cudaFuncAttributeMaxDynamicSharedMemorySize, (int)sizeof(GateSmem));

    proj_kernel<<<dim3(NROW / 32, 3), 256, sizeof(ProjSmem)>>>(x, h, Wq, bq, Wk, bk, Wv, bv);
    attn_kernel<<<dim3(Nn / 16, Bb), 256, sizeof(AttnSmem)>>>(adj);
    gate_ru_kernel<<<dim3(Kk / 64, 2), 256, sizeof(GateSmem)>>>(qv, nodes, W_r, b_r, W_u, b_u, h);
    gate_c_kernel<<<dim3(Kk / 64, 1), 256, sizeof(GateSmem)>>>(x, qv, nodes, W_c, b_c, out);
}

// round 2
// speedup vs baseline: 2.7127x; 2.7127x over previous
#include <cuda_runtime.h>
#include <math.h>

#define Hh 2
#define Bb 8
#define Nn 2048
#define Dd 64
#define Qq 16
#define Cc 129
#define C8v 16
#define Kk 8192
#define VP 132
#define NEGV (-9.0e15f)
#define NROW (Bb*Nn)
#define RT 64
#define MT 64
#define NTILE (Nn/MT)

// ---------------- device scratch ----------------
__device__ float g_q[Hh*NROW*C8v];
__device__ float g_k[Hh*NROW*C8v];
__device__ float g_v[Hh*NROW*VP];
__device__ float g_comb[NROW*VP];
__device__ float g_u[Kk*Dd];
__device__ float g_hsel[Kk*Dd];
__device__ float g_cx[Kk*Dd];
__device__ int   g_batch_flag[Bb];
__device__ int   g_tile_flag[NROW/RT];

// ---------------- cp.async helpers ----------------
__device__ __forceinline__ unsigned smem_u32(const void* p) {
    return (unsigned)__cvta_generic_to_shared(p);
}
__device__ __forceinline__ void cp16(void* dst, const void* src) {
    asm volatile("cp.async.cg.shared.global [%0], [%1], 16;\n"
                 :: "r"(smem_u32(dst)), "l"(src));
}
__device__ __forceinline__ void cp_commit() { asm volatile("cp.async.commit_group;\n"); }
template<int N> __device__ __forceinline__ void cp_wait() {
    asm volatile("cp.async.wait_group %0;\n" :: "n"(N));
}

// ---------------- flags ----------------
__global__ void flag_zero_kernel() {
    int t = threadIdx.x;
    if (t < Bb) g_batch_flag[t] = 0;
    for (int i = t; i < NROW/RT; i += 256) g_tile_flag[i] = 0;
}
__global__ void flag_mark_kernel(const int* __restrict__ nodes) {
    int i = blockIdx.x * 256 + threadIdx.x;
    if (i < Kk) {
        int row = nodes[i];
        g_tile_flag[row >> 6] = 1;
        g_batch_flag[row >> 11] = 1;
    }
}

// =================== 1) QKV projection ===================
struct ProjSmem {
    float comb[Cc][36];
    float W[Cc][VP];
    float bias[VP];
};

__global__ void proj_kernel(const float* __restrict__ x, const float* __restrict__ h,
                            const float* __restrict__ Wq, const float* __restrict__ bq,
                            const float* __restrict__ Wk, const float* __restrict__ bk,
                            const float* __restrict__ Wv, const float* __restrict__ bv) {
    extern __shared__ char sm_raw[];
    ProjSmem& sm = *reinterpret_cast<ProjSmem*>(sm_raw);
    const int t = threadIdx.x;
    const int row0 = blockIdx.x * 32;
    if (!g_batch_flag[row0 >> 11]) return;
    const int y = blockIdx.y;

    for (int idx = t; idx < 32 * Cc; idx += 256) {
        int r = idx / Cc, c = idx % Cc;
        int row = row0 + r;
        float v = (c < 65) ? x[row * 65 + c] : h[row * 64 + (c - 65)];
        sm.comb[c][r] = v;
    }
    if (y == 0) {
        for (int idx = t; idx < Cc * 64; idx += 256) {
            int c = idx / 64, o = idx % 64;
            float w;
            if (o < 32)      w = Wq[((o >> 4) * Cc + c) * C8v + (o & 15)];
            else { int o2 = o - 32; w = Wk[((o2 >> 4) * Cc + c) * C8v + (o2 & 15)]; }
            sm.W[c][o] = w;
        }
        if (t < 64) {
            float b;
            if (t < 32)      b = bq[(t >> 4) * C8v + (t & 15)];
            else { int o2 = t - 32; b = bk[(o2 >> 4) * C8v + (o2 & 15)]; }
            sm.bias[t] = b;
        }
    } else {
        int hh = y - 1;
        for (int idx = t; idx < Cc * VP; idx += 256) {
            int c = idx / VP, o = idx % VP;
            sm.W[c][o] = (o < Cc) ? Wv[(hh * Cc + c) * Cc + o] : 0.f;
        }
        for (int o = t; o < VP; o += 256) sm.bias[o] = (o < Cc) ? bv[hh * Cc + o] : 0.f;
    }
    __syncthreads();

    if (y == 0) {
        int r = t >> 3, og = t & 7;
        int c0 = og * 8;
        float acc[8];
#pragma unroll
        for (int j = 0; j < 8; j++) acc[j] = 0.f;
        for (int c = 0; c < Cc; c++) {
            float a = sm.comb[c][r];
#pragma unroll
            for (int j = 0; j < 8; j++) acc[j] += a * sm.W[c][c0 + j];
        }
        int row = row0 + r;
#pragma unroll
        for (int j = 0; j < 8; j++) {
            int o = c0 + j;
            float val = acc[j] + sm.bias[o];
            if (o < 32) {
                g_q[(((o >> 4) * NROW) + row) * C8v + (o & 15)] = val;
            } else {
                int o2 = o - 32;
                g_k[(((o2 >> 4) * NROW) + row) * C8v + (o2 & 15)] = val;
            }
        }
    } else {
        int hh = y - 1;
        int r = t >> 3, og = t & 7;
        int c0 = og * 16;
        int xcol = 128 + og;
        float acc[17];
#pragma unroll
        for (int j = 0; j < 17; j++) acc[j] = 0.f;
        for (int c = 0; c < Cc; c++) {
            float a = sm.comb[c][r];
#pragma unroll
            for (int j = 0; j < 16; j++) acc[j] += a * sm.W[c][c0 + j];
            if (og < 4) acc[16] += a * sm.W[c][xcol];
        }
        int row = row0 + r;
        float* dst = &g_v[((hh * NROW) + row) * VP];
#pragma unroll
        for (int j = 0; j < 16; j++) dst[c0 + j] = acc[j] + sm.bias[c0 + j];
        if (og < 4) dst[xcol] = acc[16] + sm.bias[xcol];
    }
}

// =================== 2) attention (register tiled, double-buffered) ===================
struct AttnSmem {
    float v[2][Hh][MT][VP];      // 135168 B
    float k[2][Hh][MT][C8v];     //  16384 B
    int   adj[2][RT][68];        //  34816 B (padded rows, 16B-aligned stride)
    float p[Hh][MT][RT];         //  32768 B (transposed: [m][r])
    float rmax[Hh][RT];
    float rsum[Hh][RT];
    float fac[Hh][RT];
};

__device__ __forceinline__ void attn_prefetch(AttnSmem& sm, int buf, int b, int row0,
                                              int m0, const int* __restrict__ adjg, int t) {
    for (int idx = t; idx < Hh * MT * 33; idx += 256) {
        int h_ = idx / (MT * 33), rem = idx % (MT * 33), m = rem / 33, c4 = rem % 33;
        cp16(&sm.v[buf][h_][m][c4 * 4],
             &g_v[((h_ * NROW) + b * Nn + m0 + m) * VP + c4 * 4]);
    }
    for (int idx = t; idx < Hh * MT * 4; idx += 256) {
        int h_ = idx / (MT * 4), rem = idx % (MT * 4), m = rem >> 2, d4 = rem & 3;
        cp16(&sm.k[buf][h_][m][d4 * 4],
             &g_k[((h_ * NROW) + b * Nn + m0 + m) * C8v + d4 * 4]);
    }
    for (int idx = t; idx < RT * 16; idx += 256) {
        int r = idx >> 4, c4 = idx & 15;
        cp16(&sm.adj[buf][r][c4 * 4],
             &adjg[(b * Nn + row0 + r) * Nn + m0 + c4 * 4]);
    }
}

__global__ void __launch_bounds__(256, 1) attn_kernel(const int* __restrict__ adjg) {
    extern __shared__ char sm_raw[];
    AttnSmem& sm = *reinterpret_cast<AttnSmem*>(sm_raw);
    const int t = threadIdx.x;
    const int b = blockIdx.y;
    const int row0 = blockIdx.x * RT;
    if (!g_tile_flag[(b * Nn + row0) >> 6]) return;

    // score mapping: (hh, row, half of keys)
    const int s_hh = t >> 7, s_r = (t & 127) >> 1, s_half = t & 1;
    // PV mapping: 8 rows x 8 cols per thread
    const int p_hh = t >> 7;
    const int t7 = t & 127;
    const int r0 = (t7 >> 4) * 8, c0 = (t7 & 15) * 8;
    // col-128 mapping (threads 0..127)
    const int x_hh = t >> 6, x_r = t & 63;

    float qreg[16];
    {
        const float4* qsrc = (const float4*)&g_q[((s_hh * NROW) + b * Nn + row0 + s_r) * C8v];
#pragma unroll
        for (int j = 0; j < 4; j++) {
            float4 qq = qsrc[j];
            qreg[4 * j] = qq.x; qreg[4 * j + 1] = qq.y;
            qreg[4 * j + 2] = qq.z; qreg[4 * j + 3] = qq.w;
        }
    }
    if (t < 128) { sm.rmax[x_hh][x_r] = -INFINITY; sm.rsum[x_hh][x_r] = 0.f; }

    float acc[8][8];
#pragma unroll
    for (int i = 0; i < 8; i++)
#pragma unroll
        for (int j = 0; j < 8; j++) acc[i][j] = 0.f;
    float acc128 = 0.f;

    attn_prefetch(sm, 0, b, row0, 0, adjg, t);
    cp_commit();

    for (int mt = 0; mt < NTILE; mt++) {
        const int buf = mt & 1;
        if (mt + 1 < NTILE) attn_prefetch(sm, buf ^ 1, b, row0, (mt + 1) * MT, adjg, t);
        cp_commit();
        cp_wait<1>();
        __syncthreads();

        // ---- scores ----
        {
#pragma unroll 4
            for (int i = 0; i < 32; i++) {
                int m = s_half * 32 + i;
                const float4* k4 = (const float4*)&sm.k[buf][s_hh][m][0];
                float s = 0.f;
#pragma unroll
                for (int d4 = 0; d4 < 4; d4++) {
                    float4 kk = k4[d4];
                    s += qreg[4 * d4] * kk.x + qreg[4 * d4 + 1] * kk.y
                       + qreg[4 * d4 + 2] * kk.z + qreg[4 * d4 + 3] * kk.w;
                }
                s *= 0.25f;
                s = (s > 0.f) ? s : 0.2f * s;
                if (sm.adj[buf][s_r][m] == 0) s = NEGV;
                sm.p[s_hh][m][s_r] = s;
            }
        }
        __syncthreads();

        // ---- online softmax (two passes; pair of threads per row) ----
        {
            int pr = t >> 1;
            int ph = pr >> 6, rr = pr & 63, hf = t & 1;
            float tmax = -INFINITY;
#pragma unroll 4
            for (int j = 0; j < 32; j++)
                tmax = fmaxf(tmax, sm.p[ph][hf * 32 + j][rr]);
            tmax = fmaxf(tmax, __shfl_xor_sync(0xffffffffu, tmax, 1));
            float oldmax = sm.rmax[ph][rr];
            float nmax = fmaxf(oldmax, tmax);
            float ssum = 0.f;
#pragma unroll 4
            for (int j = 0; j < 32; j++) {
                int m = hf * 32 + j;
                float e = __expf(sm.p[ph][m][rr] - nmax);
                sm.p[ph][m][rr] = e;
                ssum += e;
            }
            ssum += __shfl_xor_sync(0xffffffffu, ssum, 1);
            if (hf == 0) {
                float f = __expf(oldmax - nmax);
                sm.fac[ph][rr] = f;
                sm.rsum[ph][rr] = sm.rsum[ph][rr] * f + ssum;
                sm.rmax[ph][rr] = nmax;
            }
        }
        __syncthreads();

        // ---- PV accumulate ----
        {
            float f8[8];
#pragma unroll
            for (int i = 0; i < 8; i++) f8[i] = sm.fac[p_hh][r0 + i];
#pragma unroll
            for (int i = 0; i < 8; i++)
#pragma unroll
                for (int j = 0; j < 8; j++) acc[i][j] *= f8[i];
            if (t < 128) acc128 *= sm.fac[x_hh][x_r];

#pragma unroll 2
            for (int m = 0; m < MT; m++) {
                float4 p0 = *(const float4*)&sm.p[p_hh][m][r0];
                float4 p1 = *(const float4*)&sm.p[p_hh][m][r0 + 4];
                float4 v0 = *(const float4*)&sm.v[buf][p_hh][m][c0];
                float4 v1 = *(const float4*)&sm.v[buf][p_hh][m][c0 + 4];
                float pv[8] = {p0.x, p0.y, p0.z, p0.w, p1.x, p1.y, p1.z, p1.w};
                float vv[8] = {v0.x, v0.y, v0.z, v0.w, v1.x, v1.y, v1.z, v1.w};
#pragma unroll
                for (int i = 0; i < 8; i++)
#pragma unroll
                    for (int j = 0; j < 8; j++) acc[i][j] += pv[i] * vv[j];
            }
            if (t < 128) {
#pragma unroll 4
                for (int m = 0; m < MT; m++)
                    acc128 += sm.p[x_hh][m][x_r] * sm.v[buf][x_hh][m][128];
            }
        }
        __syncthreads();
    }

    // ---- finalize: mean over heads into osh, write g_comb ----
    float inv8[8];
#pragma unroll
    for (int i = 0; i < 8; i++) inv8[i] = 0.5f / sm.rsum[p_hh][r0 + i];

    float* osh = (float*)&sm.v[0][0][0][0];   // reuse v buffer
    if (p_hh == 0) {
#pragma unroll
        for (int i = 0; i < 8; i++)
#pragma unroll
            for (int j = 0; j < 8; j++)
                osh[(r0 + i) * VP + (c0 + j)] = acc[i][j] * inv8[i];
    }
    if (t < 64) osh[x_r * VP + 128] = acc128 * (0.5f / sm.rsum[0][x_r]);
    __syncthreads();
    if (p_hh == 1) {
#pragma unroll
        for (int i = 0; i < 8; i++)
#pragma unroll
            for (int j = 0; j < 8; j++)
                osh[(r0 + i) * VP + (c0 + j)] += acc[i][j] * inv8[i];
    }
    if (t >= 64 && t < 128) osh[x_r * VP + 128] += acc128 * (0.5f / sm.rsum[1][x_r]);
    __syncthreads();

    for (int idx = t; idx < RT * Cc; idx += 256) {
        int r = idx / Cc, c = idx % Cc;
        g_comb[(b * Nn + row0 + r) * VP + c] = osh[r * VP + c];
    }
}

// =================== 3a) gates r, u, cand_x (grid y = 3) ===================
struct GateASmem {
    float sel[Cc][68];
    float qv[Qq][64];
    float W[2][Cc][64];
    int   nodes[64];
};

__global__ void __launch_bounds__(256, 1) gateA_kernel(
    const float* __restrict__ qv_g, const int* __restrict__ nodes,
    const float* __restrict__ x_g, const float* __restrict__ h_g,
    const float* __restrict__ W_r, const float* __restrict__ b_r,
    const float* __restrict__ W_u, const float* __restrict__ b_u,
    const float* __restrict__ W_c, const float* __restrict__ b_c) {
    extern __shared__ char sm_raw[];
    GateASmem& sm = *reinterpret_cast<GateASmem*>(sm_raw);
    const int t = threadIdx.x;
    const int k0 = blockIdx.x * 64;
    const int g = blockIdx.y;
    const float* W    = (g == 0) ? W_r : (g == 1) ? W_u : W_c;
    const float* bias = (g == 0) ? b_r : (g == 1) ? b_u : b_c;
    const int CN = (g == 2) ? 65 : Cc;
    const int NCH = CN * 16;

    if (t < 64) sm.nodes[t] = nodes[k0 + t];
    __syncthreads();
    if (g == 2) {
        for (int idx = t; idx < 64 * 65; idx += 256) {
            int r = idx / 65, c = idx % 65;
            sm.sel[c][r] = x_g[sm.nodes[r] * 65 + c];
        }
    } else {
        for (int idx = t; idx < 64 * Cc; idx += 256) {
            int r = idx / Cc, c = idx % Cc;
            sm.sel[c][r] = g_comb[sm.nodes[r] * VP + c];
        }
    }
    for (int idx = t; idx < 64 * Qq; idx += 256) {
        int r = idx / Qq, q = idx % Qq;
        sm.qv[q][r] = qv_g[(k0 + r) * Qq + q];
    }
    // prefetch W for q=0
    for (int idx = t; idx < NCH; idx += 256)
        cp16(&sm.W[0][idx / 16][(idx % 16) * 4], &W[(idx / 16) * 64 + (idx % 16) * 4]);
    cp_commit();

    const int rg = t >> 4, og = t & 15;
    const int r0 = rg * 4, o0 = og * 4;
    float acc[4][4];
#pragma unroll
    for (int i = 0; i < 4; i++)
#pragma unroll
        for (int j = 0; j < 4; j++) acc[i][j] = 0.f;

    for (int q = 0; q < Qq; q++) {
        const int buf = q & 1;
        if (q + 1 < Qq) {
            for (int idx = t; idx < NCH; idx += 256)
                cp16(&sm.W[buf ^ 1][idx / 16][(idx % 16) * 4],
                     &W[((q + 1) * Cc + idx / 16) * 64 + (idx % 16) * 4]);
        }
        cp_commit();
        cp_wait<1>();
        __syncthreads();

        float a2[4][4];
#pragma unroll
        for (int i = 0; i < 4; i++)
#pragma unroll
            for (int j = 0; j < 4; j++) a2[i][j] = 0.f;
        for (int c = 0; c < CN; c++) {
            float4 a = *(const float4*)&sm.sel[c][r0];
            float4 w = *(const float4*)&sm.W[buf][c][o0];
            float av[4] = {a.x, a.y, a.z, a.w};
            float wv[4] = {w.x, w.y, w.z, w.w};
#pragma unroll
            for (int i = 0; i < 4; i++)
#pragma unroll
                for (int j = 0; j < 4; j++) a2[i][j] += av[i] * wv[j];
        }
        float4 qq = *(const float4*)&sm.qv[q][r0];
        float qvv[4] = {qq.x, qq.y, qq.z, qq.w};
#pragma unroll
        for (int i = 0; i < 4; i++)
#pragma unroll
            for (int j = 0; j < 4; j++) acc[i][j] += qvv[i] * a2[i][j];
        __syncthreads();
    }
    // bias: + qv @ b
    for (int q = 0; q < Qq; q++) {
        float4 bb = *(const float4*)&bias[q * 64 + o0];
        float bv4[4] = {bb.x, bb.y, bb.z, bb.w};
        float4 qq = *(const float4*)&sm.qv[q][r0];
        float qvv[4] = {qq.x, qq.y, qq.z, qq.w};
#pragma unroll
        for (int i = 0; i < 4; i++)
#pragma unroll
            for (int j = 0; j < 4; j++) acc[i][j] += qvv[i] * bv4[j];
    }
#pragma unroll
    for (int i = 0; i < 4; i++) {
        int kidx = k0 + r0 + i;
#pragma unroll
        for (int j = 0; j < 4; j++) {
            int o = o0 + j;
            if (g == 0) {
                float z = 1.f / (1.f + __expf(-acc[i][j]));
                g_hsel[kidx * 64 + o] = z * h_g[sm.nodes[r0 + i] * 64 + o];
            } else if (g == 1) {
                g_u[kidx * 64 + o] = 1.f / (1.f + __expf(-acc[i][j]));
            } else {
                g_cx[kidx * 64 + o] = acc[i][j];
            }
        }
    }
}

// =================== 3b) cand h-part + final combine ===================
struct GateBSmem {
    float sel[64][68];
    float qv[Qq][64];
    float W[2][64][64];
};

__global__ void __launch_bounds__(256, 1) gateB_kernel(
    const float* __restrict__ qv_g, const float* __restrict__ W_c,
    float* __restrict__ out) {
    extern __shared__ char sm_raw[];
    GateBSmem& sm = *reinterpret_cast<GateBSmem*>(sm_raw);
    const int t = threadIdx.x;
    const int k0 = blockIdx.x * 64;

    for (int idx = t; idx < 64 * 64; idx += 256) {
        int r = idx / 64, c = idx % 64;
        sm.sel[c][r] = g_hsel[(k0 + r) * 64 + c];
    }
    for (int idx = t; idx < 64 * Qq; idx += 256) {
        int r = idx / Qq, q = idx % Qq;
        sm.qv[q][r] = qv_g[(k0 + r) * Qq + q];
    }
    for (int idx = t; idx < 64 * 16; idx += 256)
        cp16(&sm.W[0][idx / 16][(idx % 16) * 4],
             &W_c[(65 + idx / 16) * 64 + (idx % 16) * 4]);
    cp_commit();

    const int rg = t >> 4, og = t & 15;
    const int r0 = rg * 4, o0 = og * 4;
    float acc[4][4];
#pragma unroll
    for (int i = 0; i < 4; i++)
#pragma unroll
        for (int j = 0; j < 4; j++) acc[i][j] = 0.f;

    for (int q = 0; q < Qq; q++) {
        const int buf = q & 1;
        if (q + 1 < Qq) {
            for (int idx = t; idx < 64 * 16; idx += 256)
                cp16(&sm.W[buf ^ 1][idx / 16][(idx % 16) * 4],
                     &W_c[((q + 1) * Cc + 65 + idx / 16) * 64 + (idx % 16) * 4]);
        }
        cp_commit();
        cp_wait<1>();
        __syncthreads();

        float a2[4][4];
#pragma unroll
        for (int i = 0; i < 4; i++)
#pragma unroll
            for (int j = 0; j < 4; j++) a2[i][j] = 0.f;
        for (int c = 0; c < 64; c++) {
            float4 a = *(const float4*)&sm.sel[c][r0];
            float4 w = *(const float4*)&sm.W[buf][c][o0];
            float av[4] = {a.x, a.y, a.z, a.w};
            float wv[4] = {w.x, w.y, w.z, w.w};
#pragma unroll
            for (int i = 0; i < 4; i++)
#pragma unroll
                for (int j = 0; j < 4; j++) a2[i][j] += av[i] * wv[j];
        }
        float4 qq = *(const float4*)&sm.qv[q][r0];
        float qvv[4] = {qq.x, qq.y, qq.z, qq.w};
#pragma unroll
        for (int i = 0; i < 4; i++)
#pragma unroll
            for (int j = 0; j < 4; j++) acc[i][j] += qvv[i] * a2[i][j];
        __syncthreads();
    }
#pragma unroll
    for (int i = 0; i < 4; i++) {
        int kidx = k0 + r0 + i;
#pragma unroll
        for (int j = 0; j < 4; j++) {
            int o = o0 + j;
            float raw = g_cx[kidx * 64 + o] + acc[i][j];
            float cand = tanhf(raw);
            float u  = g_u[kidx * 64 + o];
            float hs = g_hsel[kidx * 64 + o];
            out[kidx * 64 + o] = (1.f - u) * hs + u * cand;
        }
    }
}

// =================== launch ===================
extern "C" void kernel_launch(void* const* d_in, const int* in_sizes, int n_in,
                              void* d_out, int out_size) {
    const float* x   = (const float*)d_in[0];
    const float* h   = (const float*)d_in[1];
    const float* qv  = (const float*)d_in[2];
    const int*   adj = (const int*)d_in[3];
    const int*   nodes = (const int*)d_in[4];
    const float* Wq = (const float*)d_in[5];
    const float* bq = (const float*)d_in[6];
    const float* Wk = (const float*)d_in[7];
    const float* bk = (const float*)d_in[8];
    const float* Wv = (const float*)d_in[9];
    const float* bv = (const float*)d_in[10];
    const float* W_r = (const float*)d_in[11];
    const float* b_r = (const float*)d_in[12];
    const float* W_u = (const float*)d_in[13];
    const float* b_u = (const float*)d_in[14];
    const float* W_c = (const float*)d_in[15];
    const float* b_c = (const float*)d_in[16];
    float* out = (float*)d_out;

    cudaFuncSetAttribute(proj_kernel, cudaFuncAttributeMaxDynamicSharedMemorySize, (int)sizeof(ProjSmem));
    cudaFuncSetAttribute(attn_kernel, cudaFuncAttributeMaxDynamicSharedMemorySize, (int)sizeof(AttnSmem));
    cudaFuncSetAttribute(gateA_kernel, cudaFuncAttributeMaxDynamicSharedMemorySize, (int)sizeof(GateASmem));
    cudaFuncSetAttribute(gateB_kernel, cudaFuncAttributeMaxDynamicSharedMemorySize, (int)sizeof(GateBSmem));

    flag_zero_kernel<<<1, 256>>>();
    flag_mark_kernel<<<Kk / 256, 256>>>(nodes);
    proj_kernel<<<dim3(NROW / 32, 3), 256, sizeof(ProjSmem)>>>(x, h, Wq, bq, Wk, bk, Wv, bv);
    attn_kernel<<<dim3(Nn / RT, Bb), 256, sizeof(AttnSmem)>>>(adj);
    gateA_kernel<<<dim3(Kk / 64, 3), 256, sizeof(GateASmem)>>>(qv, nodes, x, h,
                                                               W_r, b_r, W_u, b_u, W_c, b_c);
    gateB_kernel<<<dim3(Kk / 64, 1), 256, sizeof(GateBSmem)>>>(qv, W_c, out);
}

// round 3
// speedup vs baseline: 2.7943x; 1.0301x over previous
#include <cuda_runtime.h>
#include <math.h>

#define Hh 2
#define Bb 8
#define Nn 2048
#define Dd 64
#define Qq 16
#define Cc 129
#define C8v 16
#define Kk 8192
#define VP 132
#define NEGV (-9.0e15f)
#define NROW (Bb*Nn)
#define RT 64
#define MT 64
#define NTILE (Nn/MT)

// ---------------- packed f32x2 helpers (Blackwell) ----------------
typedef unsigned long long u64t;
#define PACK2(out, lo, hi) \
    asm("mov.b64 %0, {%1, %2};" : "=l"(out) : "f"(lo), "f"(hi))
#define UNPACK2(lo, hi, in) \
    asm("mov.b64 {%0, %1}, %2;" : "=f"(lo), "=f"(hi) : "l"(in))
#define FMA2(d, a, b, c) \
    asm("fma.rn.f32x2 %0, %1, %2, %3;" : "=l"(d) : "l"(a), "l"(b), "l"(c))
#define MUL2(d, a, b) \
    asm("mul.rn.f32x2 %0, %1, %2;" : "=l"(d) : "l"(a), "l"(b))

// ---------------- device scratch ----------------
__device__ float g_q[Hh*NROW*C8v];
__device__ float g_k[Hh*NROW*C8v];
__device__ float g_v[Hh*NROW*VP];
__device__ float g_comb[NROW*VP];
__device__ float g_u[Kk*Dd];
__device__ float g_hsel[Kk*Dd];
__device__ float g_cx[Kk*Dd];
__device__ int   g_batch_flag[Bb];
__device__ int   g_tile_flag[NROW/RT];

// ---------------- cp.async helpers ----------------
__device__ __forceinline__ unsigned smem_u32(const void* p) {
    return (unsigned)__cvta_generic_to_shared(p);
}
__device__ __forceinline__ void cp16(void* dst, const void* src) {
    asm volatile("cp.async.cg.shared.global [%0], [%1], 16;\n"
                 :: "r"(smem_u32(dst)), "l"(src));
}
__device__ __forceinline__ void cp_commit() { asm volatile("cp.async.commit_group;\n"); }
template<int N> __device__ __forceinline__ void cp_wait() {
    asm volatile("cp.async.wait_group %0;\n" :: "n"(N));
}

// ---------------- flags ----------------
__global__ void flag_zero_kernel() {
    int t = threadIdx.x;
    if (t < Bb) g_batch_flag[t] = 0;
    for (int i = t; i < NROW/RT; i += 256) g_tile_flag[i] = 0;
}
__global__ void flag_mark_kernel(const int* __restrict__ nodes) {
    int i = blockIdx.x * 256 + threadIdx.x;
    if (i < Kk) {
        int row = nodes[i];
        g_tile_flag[row >> 6] = 1;
        g_batch_flag[row >> 11] = 1;
    }
}

// =================== 1) QKV projection ===================
struct ProjSmem {
    float comb[Cc][36];
    float W[Cc][VP];
    float bias[VP];
};

__global__ void proj_kernel(const float* __restrict__ x, const float* __restrict__ h,
                            const float* __restrict__ Wq, const float* __restrict__ bq,
                            const float* __restrict__ Wk, const float* __restrict__ bk,
                            const float* __restrict__ Wv, const float* __restrict__ bv) {
    extern __shared__ char sm_raw[];
    ProjSmem& sm = *reinterpret_cast<ProjSmem*>(sm_raw);
    const int t = threadIdx.x;
    const int row0 = blockIdx.x * 32;
    if (!g_batch_flag[row0 >> 11]) return;
    const int y = blockIdx.y;

    for (int idx = t; idx < 32 * Cc; idx += 256) {
        int r = idx / Cc, c = idx % Cc;
        int row = row0 + r;
        float v = (c < 65) ? x[row * 65 + c] : h[row * 64 + (c - 65)];
        sm.comb[c][r] = v;
    }
    if (y == 0) {
        for (int idx = t; idx < Cc * 64; idx += 256) {
            int c = idx / 64, o = idx % 64;
            float w;
            if (o < 32)      w = Wq[((o >> 4) * Cc + c) * C8v + (o & 15)];
            else { int o2 = o - 32; w = Wk[((o2 >> 4) * Cc + c) * C8v + (o2 & 15)]; }
            sm.W[c][o] = w;
        }
        if (t < 64) {
            float b;
            if (t < 32)      b = bq[(t >> 4) * C8v + (t & 15)];
            else { int o2 = t - 32; b = bk[(o2 >> 4) * C8v + (o2 & 15)]; }
            sm.bias[t] = b;
        }
    } else {
        int hh = y - 1;
        for (int idx = t; idx < Cc * VP; idx += 256) {
            int c = idx / VP, o = idx % VP;
            sm.W[c][o] = (o < Cc) ? Wv[(hh * Cc + c) * Cc + o] : 0.f;
        }
        for (int o = t; o < VP; o += 256) sm.bias[o] = (o < Cc) ? bv[hh * Cc + o] : 0.f;
    }
    __syncthreads();

    if (y == 0) {
        int r = t >> 3, og = t & 7;
        int c0 = og * 8;
        float acc[8];
#pragma unroll
        for (int j = 0; j < 8; j++) acc[j] = 0.f;
        for (int c = 0; c < Cc; c++) {
            float a = sm.comb[c][r];
#pragma unroll
            for (int j = 0; j < 8; j++) acc[j] += a * sm.W[c][c0 + j];
        }
        int row = row0 + r;
#pragma unroll
        for (int j = 0; j < 8; j++) {
            int o = c0 + j;
            float val = acc[j] + sm.bias[o];
            if (o < 32) {
                g_q[(((o >> 4) * NROW) + row) * C8v + (o & 15)] = val;
            } else {
                int o2 = o - 32;
                g_k[(((o2 >> 4) * NROW) + row) * C8v + (o2 & 15)] = val;
            }
        }
    } else {
        int hh = y - 1;
        int r = t >> 3, og = t & 7;
        int c0 = og * 16;
        int xcol = 128 + og;
        float acc[17];
#pragma unroll
        for (int j = 0; j < 17; j++) acc[j] = 0.f;
        for (int c = 0; c < Cc; c++) {
            float a = sm.comb[c][r];
#pragma unroll
            for (int j = 0; j < 16; j++) acc[j] += a * sm.W[c][c0 + j];
            if (og < 4) acc[16] += a * sm.W[c][xcol];
        }
        int row = row0 + r;
        float* dst = &g_v[((hh * NROW) + row) * VP];
#pragma unroll
        for (int j = 0; j < 16; j++) dst[c0 + j] = acc[j] + sm.bias[c0 + j];
        if (og < 4) dst[xcol] = acc[16] + sm.bias[xcol];
    }
}

// =================== 2) attention (f32x2 register tiled, double-buffered) ===================
struct AttnSmem {
    float v[2][Hh][MT][VP];
    float k[2][Hh][MT][C8v];
    int   adj[2][RT][68];
    float p[Hh][MT][RT];
    float rmax[Hh][RT];
    float rsum[Hh][RT];
    float fac[Hh][RT];
};

__device__ __forceinline__ void attn_prefetch(AttnSmem& sm, int buf, int b, int row0,
                                              int m0, const int* __restrict__ adjg, int t) {
    for (int idx = t; idx < Hh * MT * 33; idx += 256) {
        int h_ = idx / (MT * 33), rem = idx % (MT * 33), m = rem / 33, c4 = rem % 33;
        cp16(&sm.v[buf][h_][m][c4 * 4],
             &g_v[((h_ * NROW) + b * Nn + m0 + m) * VP + c4 * 4]);
    }
    for (int idx = t; idx < Hh * MT * 4; idx += 256) {
        int h_ = idx / (MT * 4), rem = idx % (MT * 4), m = rem >> 2, d4 = rem & 3;
        cp16(&sm.k[buf][h_][m][d4 * 4],
             &g_k[((h_ * NROW) + b * Nn + m0 + m) * C8v + d4 * 4]);
    }
    for (int idx = t; idx < RT * 16; idx += 256) {
        int r = idx >> 4, c4 = idx & 15;
        cp16(&sm.adj[buf][r][c4 * 4],
             &adjg[(b * Nn + row0 + r) * Nn + m0 + c4 * 4]);
    }
}

__global__ void __launch_bounds__(256, 1) attn_kernel(const int* __restrict__ adjg) {
    extern __shared__ char sm_raw[];
    AttnSmem& sm = *reinterpret_cast<AttnSmem*>(sm_raw);
    const int t = threadIdx.x;
    const int b = blockIdx.y;
    const int row0 = blockIdx.x * RT;
    if (!g_tile_flag[(b * Nn + row0) >> 6]) return;

    const int s_hh = t >> 7, s_r = (t & 127) >> 1, s_half = t & 1;
    const int p_hh = t >> 7;
    const int t7 = t & 127;
    const int r0 = (t7 >> 4) * 8, c0 = (t7 & 15) * 8;
    const int x_hh = t >> 6, x_r = t & 63;

    float qreg[16];
    {
        const float4* qsrc = (const float4*)&g_q[((s_hh * NROW) + b * Nn + row0 + s_r) * C8v];
#pragma unroll
        for (int j = 0; j < 4; j++) {
            float4 qq = qsrc[j];
            qreg[4 * j] = qq.x; qreg[4 * j + 1] = qq.y;
            qreg[4 * j + 2] = qq.z; qreg[4 * j + 3] = qq.w;
        }
    }
    if (t < 128) { sm.rmax[x_hh][x_r] = -INFINITY; sm.rsum[x_hh][x_r] = 0.f; }

    u64t acc2[8][4];   // [row][col-pair], packed f32x2
#pragma unroll
    for (int i = 0; i < 8; i++)
#pragma unroll
        for (int j = 0; j < 4; j++) acc2[i][j] = 0ull;
    float acc128 = 0.f;

    attn_prefetch(sm, 0, b, row0, 0, adjg, t);
    cp_commit();

    for (int mt = 0; mt < NTILE; mt++) {
        const int buf = mt & 1;
        if (mt + 1 < NTILE) attn_prefetch(sm, buf ^ 1, b, row0, (mt + 1) * MT, adjg, t);
        cp_commit();
        cp_wait<1>();
        __syncthreads();

        // ---- scores ----
        {
#pragma unroll 4
            for (int i = 0; i < 32; i++) {
                int m = s_half * 32 + i;
                const float4* k4 = (const float4*)&sm.k[buf][s_hh][m][0];
                float s = 0.f;
#pragma unroll
                for (int d4 = 0; d4 < 4; d4++) {
                    float4 kk = k4[d4];
                    s += qreg[4 * d4] * kk.x + qreg[4 * d4 + 1] * kk.y
                       + qreg[4 * d4 + 2] * kk.z + qreg[4 * d4 + 3] * kk.w;
                }
                s *= 0.25f;
                s = (s > 0.f) ? s : 0.2f * s;
                if (sm.adj[buf][s_r][m] == 0) s = NEGV;
                sm.p[s_hh][m][s_r] = s;
            }
        }
        __syncthreads();

        // ---- online softmax ----
        {
            int pr = t >> 1;
            int ph = pr >> 6, rr = pr & 63, hf = t & 1;
            float tmax = -INFINITY;
#pragma unroll 4
            for (int j = 0; j < 32; j++)
                tmax = fmaxf(tmax, sm.p[ph][hf * 32 + j][rr]);
            tmax = fmaxf(tmax, __shfl_xor_sync(0xffffffffu, tmax, 1));
            float oldmax = sm.rmax[ph][rr];
            float nmax = fmaxf(oldmax, tmax);
            float ssum = 0.f;
#pragma unroll 4
            for (int j = 0; j < 32; j++) {
                int m = hf * 32 + j;
                float e = __expf(sm.p[ph][m][rr] - nmax);
                sm.p[ph][m][rr] = e;
                ssum += e;
            }
            ssum += __shfl_xor_sync(0xffffffffu, ssum, 1);
            if (hf == 0) {
                float f = __expf(oldmax - nmax);
                sm.fac[ph][rr] = f;
                sm.rsum[ph][rr] = sm.rsum[ph][rr] * f + ssum;
                sm.rmax[ph][rr] = nmax;
            }
        }
        __syncthreads();

        // ---- PV accumulate (packed f32x2) ----
        {
#pragma unroll
            for (int i = 0; i < 8; i++) {
                float f = sm.fac[p_hh][r0 + i];
                u64t fd; PACK2(fd, f, f);
#pragma unroll
                for (int j = 0; j < 4; j++) MUL2(acc2[i][j], acc2[i][j], fd);
            }
            if (t < 128) acc128 *= sm.fac[x_hh][x_r];

#pragma unroll 2
            for (int m = 0; m < MT; m++) {
                float4 p0 = *(const float4*)&sm.p[p_hh][m][r0];
                float4 p1 = *(const float4*)&sm.p[p_hh][m][r0 + 4];
                float4 v0 = *(const float4*)&sm.v[buf][p_hh][m][c0];
                float4 v1 = *(const float4*)&sm.v[buf][p_hh][m][c0 + 4];
                u64t vv[4];
                PACK2(vv[0], v0.x, v0.y); PACK2(vv[1], v0.z, v0.w);
                PACK2(vv[2], v1.x, v1.y); PACK2(vv[3], v1.z, v1.w);
                float pv[8] = {p0.x, p0.y, p0.z, p0.w, p1.x, p1.y, p1.z, p1.w};
#pragma unroll
                for (int i = 0; i < 8; i++) {
                    u64t pd; PACK2(pd, pv[i], pv[i]);
#pragma unroll
                    for (int j = 0; j < 4; j++)
                        FMA2(acc2[i][j], pd, vv[j], acc2[i][j]);
                }
            }
            if (t < 128) {
#pragma unroll 4
                for (int m = 0; m < MT; m++)
                    acc128 += sm.p[x_hh][m][x_r] * sm.v[buf][x_hh][m][128];
            }
        }
        __syncthreads();
    }

    // ---- finalize: mean over heads ----
    float accf[8][8];
#pragma unroll
    for (int i = 0; i < 8; i++) {
        float inv = 0.5f / sm.rsum[p_hh][r0 + i];
#pragma unroll
        for (int j = 0; j < 4; j++) {
            float lo, hi;
            UNPACK2(lo, hi, acc2[i][j]);
            accf[i][2 * j] = lo * inv;
            accf[i][2 * j + 1] = hi * inv;
        }
    }

    float* osh = (float*)&sm.v[0][0][0][0];
    if (p_hh == 0) {
#pragma unroll
        for (int i = 0; i < 8; i++)
#pragma unroll
            for (int j = 0; j < 8; j++)
                osh[(r0 + i) * VP + (c0 + j)] = accf[i][j];
    }
    if (t < 64) osh[x_r * VP + 128] = acc128 * (0.5f / sm.rsum[0][x_r]);
    __syncthreads();
    if (p_hh == 1) {
#pragma unroll
        for (int i = 0; i < 8; i++)
#pragma unroll
            for (int j = 0; j < 8; j++)
                osh[(r0 + i) * VP + (c0 + j)] += accf[i][j];
    }
    if (t >= 64 && t < 128) osh[x_r * VP + 128] += acc128 * (0.5f / sm.rsum[1][x_r]);
    __syncthreads();

    for (int idx = t; idx < RT * Cc; idx += 256) {
        int r = idx / Cc, c = idx % Cc;
        g_comb[(b * Nn + row0 + r) * VP + c] = osh[r * VP + c];
    }
}

// =================== 3a) gates r, u, cand_x ===================
struct GateASmem {
    float sel[Cc][68];
    float qv[Qq][64];
    float W[2][Cc][64];
    int   nodes[64];
};

__global__ void __launch_bounds__(256, 1) gateA_kernel(
    const float* __restrict__ qv_g, const int* __restrict__ nodes,
    const float* __restrict__ x_g, const float* __restrict__ h_g,
    const float* __restrict__ W_r, const float* __restrict__ b_r,
    const float* __restrict__ W_u, const float* __restrict__ b_u,
    const float* __restrict__ W_c, const float* __restrict__ b_c) {
    extern __shared__ char sm_raw[];
    GateASmem& sm = *reinterpret_cast<GateASmem*>(sm_raw);
    const int t = threadIdx.x;
    const int k0 = blockIdx.x * 64;
    const int g = blockIdx.y;
    const float* W    = (g == 0) ? W_r : (g == 1) ? W_u : W_c;
    const float* bias = (g == 0) ? b_r : (g == 1) ? b_u : b_c;
    const int CN = (g == 2) ? 65 : Cc;
    const int NCH = CN * 16;

    if (t < 64) sm.nodes[t] = nodes[k0 + t];
    __syncthreads();
    if (g == 2) {
        for (int idx = t; idx < 64 * 65; idx += 256) {
            int r = idx / 65, c = idx % 65;
            sm.sel[c][r] = x_g[sm.nodes[r] * 65 + c];
        }
    } else {
        for (int idx = t; idx < 64 * Cc; idx += 256) {
            int r = idx / Cc, c = idx % Cc;
            sm.sel[c][r] = g_comb[sm.nodes[r] * VP + c];
        }
    }
    for (int idx = t; idx < 64 * Qq; idx += 256) {
        int r = idx / Qq, q = idx % Qq;
        sm.qv[q][r] = qv_g[(k0 + r) * Qq + q];
    }
    for (int idx = t; idx < NCH; idx += 256)
        cp16(&sm.W[0][idx / 16][(idx % 16) * 4], &W[(idx / 16) * 64 + (idx % 16) * 4]);
    cp_commit();

    const int rg = t >> 4, og = t & 15;
    const int r0 = rg * 4, o0 = og * 4;
    u64t acc2[4][2];
#pragma unroll
    for (int i = 0; i < 4; i++) { acc2[i][0] = 0ull; acc2[i][1] = 0ull; }

    for (int q = 0; q < Qq; q++) {
        const int buf = q & 1;
        if (q + 1 < Qq) {
            for (int idx = t; idx < NCH; idx += 256)
                cp16(&sm.W[buf ^ 1][idx / 16][(idx % 16) * 4],
                     &W[((q + 1) * Cc + idx / 16) * 64 + (idx % 16) * 4]);
        }
        cp_commit();
        cp_wait<1>();
        __syncthreads();

        u64t a2[4][2];
#pragma unroll
        for (int i = 0; i < 4; i++) { a2[i][0] = 0ull; a2[i][1] = 0ull; }
        for (int c = 0; c < CN; c++) {
            float4 a = *(const float4*)&sm.sel[c][r0];
            float4 w = *(const float4*)&sm.W[buf][c][o0];
            u64t wv0, wv1;
            PACK2(wv0, w.x, w.y); PACK2(wv1, w.z, w.w);
            float av[4] = {a.x, a.y, a.z, a.w};
#pragma unroll
            for (int i = 0; i < 4; i++) {
                u64t ad; PACK2(ad, av[i], av[i]);
                FMA2(a2[i][0], ad, wv0, a2[i][0]);
                FMA2(a2[i][1], ad, wv1, a2[i][1]);
            }
        }
        float4 qq = *(const float4*)&sm.qv[q][r0];
        float qvv[4] = {qq.x, qq.y, qq.z, qq.w};
#pragma unroll
        for (int i = 0; i < 4; i++) {
            u64t qd; PACK2(qd, qvv[i], qvv[i]);
            FMA2(acc2[i][0], qd, a2[i][0], acc2[i][0]);
            FMA2(acc2[i][1], qd, a2[i][1], acc2[i][1]);
        }
        __syncthreads();
    }

    float acc[4][4];
#pragma unroll
    for (int i = 0; i < 4; i++) {
        UNPACK2(acc[i][0], acc[i][1], acc2[i][0]);
        UNPACK2(acc[i][2], acc[i][3], acc2[i][1]);
    }
    for (int q = 0; q < Qq; q++) {
        float4 bb = *(const float4*)&bias[q * 64 + o0];
        float bv4[4] = {bb.x, bb.y, bb.z, bb.w};
        float4 qq = *(const float4*)&sm.qv[q][r0];
        float qvv[4] = {qq.x, qq.y, qq.z, qq.w};
#pragma unroll
        for (int i = 0; i < 4; i++)
#pragma unroll
            for (int j = 0; j < 4; j++) acc[i][j] += qvv[i] * bv4[j];
    }
#pragma unroll
    for (int i = 0; i < 4; i++) {
        int kidx = k0 + r0 + i;
#pragma unroll
        for (int j = 0; j < 4; j++) {
            int o = o0 + j;
            if (g == 0) {
                float z = 1.f / (1.f + __expf(-acc[i][j]));
                g_hsel[kidx * 64 + o] = z * h_g[sm.nodes[r0 + i] * 64 + o];
            } else if (g == 1) {
                g_u[kidx * 64 + o] = 1.f / (1.f + __expf(-acc[i][j]));
            } else {
                g_cx[kidx * 64 + o] = acc[i][j];
            }
        }
    }
}

// =================== 3b) cand h-part + final combine ===================
struct GateBSmem {
    float sel[64][68];
    float qv[Qq][64];
    float W[2][64][64];
};

__global__ void __launch_bounds__(256, 1) gateB_kernel(
    const float* __restrict__ qv_g, const float* __restrict__ W_c,
    float* __restrict__ out) {
    extern __shared__ char sm_raw[];
    GateBSmem& sm = *reinterpret_cast<GateBSmem*>(sm_raw);
    const int t = threadIdx.x;
    const int k0 = blockIdx.x * 64;

    for (int idx = t; idx < 64 * 64; idx += 256) {
        int r = idx / 64, c = idx % 64;
        sm.sel[c][r] = g_hsel[(k0 + r) * 64 + c];
    }
    for (int idx = t; idx < 64 * Qq; idx += 256) {
        int r = idx / Qq, q = idx % Qq;
        sm.qv[q][r] = qv_g[(k0 + r) * Qq + q];
    }
    for (int idx = t; idx < 64 * 16; idx += 256)
        cp16(&sm.W[0][idx / 16][(idx % 16) * 4],
             &W_c[(65 + idx / 16) * 64 + (idx % 16) * 4]);
    cp_commit();

    const int rg = t >> 4, og = t & 15;
    const int r0 = rg * 4, o0 = og * 4;
    u64t acc2[4][2];
#pragma unroll
    for (int i = 0; i < 4; i++) { acc2[i][0] = 0ull; acc2[i][1] = 0ull; }

    for (int q = 0; q < Qq; q++) {
        const int buf = q & 1;
        if (q + 1 < Qq) {
            for (int idx = t; idx < 64 * 16; idx += 256)
                cp16(&sm.W[buf ^ 1][idx / 16][(idx % 16) * 4],
                     &W_c[((q + 1) * Cc + 65 + idx / 16) * 64 + (idx % 16) * 4]);
        }
        cp_commit();
        cp_wait<1>();
        __syncthreads();

        u64t a2[4][2];
#pragma unroll
        for (int i = 0; i < 4; i++) { a2[i][0] = 0ull; a2[i][1] = 0ull; }
        for (int c = 0; c < 64; c++) {
            float4 a = *(const float4*)&sm.sel[c][r0];
            float4 w = *(const float4*)&sm.W[buf][c][o0];
            u64t wv0, wv1;
            PACK2(wv0, w.x, w.y); PACK2(wv1, w.z, w.w);
            float av[4] = {a.x, a.y, a.z, a.w};
#pragma unroll
            for (int i = 0; i < 4; i++) {
                u64t ad; PACK2(ad, av[i], av[i]);
                FMA2(a2[i][0], ad, wv0, a2[i][0]);
                FMA2(a2[i][1], ad, wv1, a2[i][1]);
            }
        }
        float4 qq = *(const float4*)&sm.qv[q][r0];
        float qvv[4] = {qq.x, qq.y, qq.z, qq.w};
#pragma unroll
        for (int i = 0; i < 4; i++) {
            u64t qd; PACK2(qd, qvv[i], qvv[i]);
            FMA2(acc2[i][0], qd, a2[i][0], acc2[i][0]);
            FMA2(acc2[i][1], qd, a2[i][1], acc2[i][1]);
        }
        __syncthreads();
    }

    float acc[4][4];
#pragma unroll
    for (int i = 0; i < 4; i++) {
        UNPACK2(acc[i][0], acc[i][1], acc2[i][0]);
        UNPACK2(acc[i][2], acc[i][3], acc2[i][1]);
    }
#pragma unroll
    for (int i = 0; i < 4; i++) {
        int kidx = k0 + r0 + i;
#pragma unroll
        for (int j = 0; j < 4; j++) {
            int o = o0 + j;
            float raw = g_cx[kidx * 64 + o] + acc[i][j];
            float cand = tanhf(raw);
            float u  = g_u[kidx * 64 + o];
            float hs = g_hsel[kidx * 64 + o];
            out[kidx * 64 + o] = (1.f - u) * hs + u * cand;
        }
    }
}

// =================== launch ===================
extern "C" void kernel_launch(void* const* d_in, const int* in_sizes, int n_in,
                              void* d_out, int out_size) {
    const float* x   = (const float*)d_in[0];
    const float* h   = (const float*)d_in[1];
    const float* qv  = (const float*)d_in[2];
    const int*   adj = (const int*)d_in[3];
    const int*   nodes = (const int*)d_in[4];
    const float* Wq = (const float*)d_in[5];
    const float* bq = (const float*)d_in[6];
    const float* Wk = (const float*)d_in[7];
    const float* bk = (const float*)d_in[8];
    const float* Wv = (const float*)d_in[9];
    const float* bv = (const float*)d_in[10];
    const float* W_r = (const float*)d_in[11];
    const float* b_r = (const float*)d_in[12];
    const float* W_u = (const float*)d_in[13];
    const float* b_u = (const float*)d_in[14];
    const float* W_c = (const float*)d_in[15];
    const float* b_c = (const float*)d_in[16];
    float* out = (float*)d_out;

    cudaFuncSetAttribute(proj_kernel, cudaFuncAttributeMaxDynamicSharedMemorySize, (int)sizeof(ProjSmem));
    cudaFuncSetAttribute(attn_kernel, cudaFuncAttributeMaxDynamicSharedMemorySize, (int)sizeof(AttnSmem));
    cudaFuncSetAttribute(gateA_kernel, cudaFuncAttributeMaxDynamicSharedMemorySize, (int)sizeof(GateASmem));
    cudaFuncSetAttribute(gateB_kernel, cudaFuncAttributeMaxDynamicSharedMemorySize, (int)sizeof(GateBSmem));

    flag_zero_kernel<<<1, 256>>>();
    flag_mark_kernel<<<Kk / 256, 256>>>(nodes);
    proj_kernel<<<dim3(NROW / 32, 3), 256, sizeof(ProjSmem)>>>(x, h, Wq, bq, Wk, bk, Wv, bv);
    attn_kernel<<<dim3(Nn / RT, Bb), 256, sizeof(AttnSmem)>>>(adj);
    gateA_kernel<<<dim3(Kk / 64, 3), 256, sizeof(GateASmem)>>>(qv, nodes, x, h,
                                                               W_r, b_r, W_u, b_u, W_c, b_c);
    gateB_kernel<<<dim3(Kk / 64, 1), 256, sizeof(GateBSmem)>>>(qv, W_c, out);
}